// round 1
// baseline (speedup 1.0000x reference)
#include <cuda_runtime.h>
#include <cuda_bf16.h>
#include <cstdint>

// Problem constants
#define NPIX   65536      // 64 * 32 * 32 pixels
#define HW     1024       // 32*32
#define CCH    10         // channels / token bits
#define NCODE  1024       // 2^10
#define NELEM  655360     // 64*10*32*32

// Output layout (flattened reference tuple, fp32):
//  [0, 655360)            z_q_out  (sign(z), b c h w layout)
//  [655360]               loss
//  [655361]               commitment_loss
//  [655362]               entropy_loss
//  [655363]               per_sample_entropy
//  [655364]               avg_entropy
//  [655365, 720901)       min_encoding_indices (as float)
#define OUT_SCALARS 655360
#define OUT_IDX     655365

// Entropy kernel launch shape
#define EBLOCKS 512
#define ETHREADS 256
#define EWARPS (EBLOCKS * (ETHREADS / 32))   // 4096
#define PPW (NPIX / EWARPS)                  // 16 pixels per warp

// Scratch (no allocations allowed)
__device__ float g_avg_probs[NCODE];
__device__ float g_pse_sum;     // sum over pixels of (logZ - T/Z)
__device__ float g_commit_sum;  // sum over elements of (1-|z|)^2

// ---------------------------------------------------------------------------
// Kernel 0: zero scratch (graph replays must start clean every launch)
// ---------------------------------------------------------------------------
__global__ void lfq_init_kernel() {
    int t = blockIdx.x * blockDim.x + threadIdx.x;
    if (t < NCODE) g_avg_probs[t] = 0.0f;
    if (t == 0) { g_pse_sum = 0.0f; g_commit_sum = 0.0f; }
}

// ---------------------------------------------------------------------------
// Kernel 1: sign output, indices, commitment-loss accumulation.
// One thread per pixel; reads z once, writes 10 sign values + 1 index.
// ---------------------------------------------------------------------------
__global__ __launch_bounds__(256) void lfq_signidx_kernel(
    const float* __restrict__ z, float* __restrict__ out)
{
    int p = blockIdx.x * blockDim.x + threadIdx.x;   // pixel id: b*1024 + hw
    if (p >= NPIX) return;
    int b  = p >> 10;
    int hw = p & (HW - 1);
    const float* zp = z + b * (CCH * HW) + hw;
    float*       op = out + b * (CCH * HW) + hw;

    int   idx  = 0;
    float csum = 0.0f;
#pragma unroll
    for (int c = 0; c < CCH; c++) {
        float v = __ldg(zp + c * HW);
        bool pos = v > 0.0f;
        op[c * HW] = pos ? 1.0f : -1.0f;
        idx |= (pos ? 1 : 0) << c;
        float d = 1.0f - fabsf(v);     // (sign(v) - v)^2 == (1 - |v|)^2
        csum = fmaf(d, d, csum);
    }
    out[OUT_IDX + p] = (float)idx;

    // warp-reduce commitment partial, one atomic per warp
#pragma unroll
    for (int o = 16; o; o >>= 1)
        csum += __shfl_xor_sync(0xFFFFFFFFu, csum, o);
    if ((threadIdx.x & 31) == 0)
        atomicAdd(&g_commit_sum, csum);
}

// ---------------------------------------------------------------------------
// Kernel 2: entropy. Warp per pixel, lane = low 5 bits of code (lo),
// j = high 5 bits (hi); code n = j*32 + lane.
//   dot_n = 2*(PL[lo] + PH[hi]) - S ;  max dot = sum|z|
//   delta_n = 200*dot_n - 200*sum|z| = base(lane) + h[j],  h[j] = 400*PH[j]
// ---------------------------------------------------------------------------
__global__ __launch_bounds__(ETHREADS) void lfq_entropy_kernel(
    const float* __restrict__ z)
{
    __shared__ float s_ap[NCODE];
    int tid = threadIdx.x;
    for (int i = tid; i < NCODE; i += ETHREADS) s_ap[i] = 0.0f;
    __syncthreads();

    int lane = tid & 31;
    int warp = blockIdx.x * (ETHREADS / 32) + (tid >> 5);

    float ap[32];
#pragma unroll
    for (int j = 0; j < 32; j++) ap[j] = 0.0f;
    float pse_acc = 0.0f;

    int p0 = warp * PPW;
    for (int t = 0; t < PPW; t++) {
        int p  = p0 + t;
        int b  = p >> 10;
        int hw = p & (HW - 1);
        const float* zp = z + b * (CCH * HW) + hw;

        float zc[CCH];
#pragma unroll
        for (int c = 0; c < CCH; c++) zc[c] = __ldg(zp + c * HW);

        float S = 0.0f, A = 0.0f;
#pragma unroll
        for (int c = 0; c < CCH; c++) { S += zc[c]; A += fabsf(zc[c]); }

        // PL over low 5 bits selected by this lane's id
        float myPL = 0.0f;
#pragma unroll
        for (int c = 0; c < 5; c++)
            if (lane & (1 << c)) myPL += zc[c];

        // h[j] = 400 * PH[j] via subset-sum DP (31 FADDs)
        float v5[5];
#pragma unroll
        for (int c = 0; c < 5; c++) v5[c] = 400.0f * zc[5 + c];
        float h[32];
        h[0] = 0.0f;
#pragma unroll
        for (int c = 0; c < 5; c++) {
            int s = 1 << c;
#pragma unroll
            for (int j = 0; j < 32; j++) {
                if (j < s) h[s + j] = h[j] + v5[c];
            }
        }

        float base = 400.0f * myPL - 200.0f * (S + A);   // delta = base + h[j] <= 0

        float Z = 0.0f, T = 0.0f;
#pragma unroll
        for (int j = 0; j < 32; j++) {
            float d = base + h[j];
            float e = __expf(d);
            Z += e;
            T = fmaf(e, d, T);     // sum e_i * delta_i
            h[j] = e;              // reuse register array to hold e
        }

        // reduce Z, T across the warp (full 1024-code totals)
#pragma unroll
        for (int o = 16; o; o >>= 1) {
            Z += __shfl_xor_sync(0xFFFFFFFFu, Z, o);
            T += __shfl_xor_sync(0xFFFFFFFFu, T, o);
        }

        float invZ = 1.0f / Z;
        // per-pixel entropy: -(sum p log p) = logZ - T/Z (accurate log; once/pixel)
        pse_acc += logf(Z) - T * invZ;

#pragma unroll
        for (int j = 0; j < 32; j++)
            ap[j] = fmaf(h[j], invZ, ap[j]);   // accumulate probs
    }

    // pse: all lanes hold identical pse_acc; lane 0 flushes
    if (lane == 0) atomicAdd(&g_pse_sum, pse_acc);

    // avg_probs: block smem stage (bank-conflict-free: bank = lane), then global
#pragma unroll
    for (int j = 0; j < 32; j++)
        atomicAdd(&s_ap[j * 32 + lane], ap[j]);
    __syncthreads();
    for (int i = tid; i < NCODE; i += ETHREADS)
        atomicAdd(&g_avg_probs[i], s_ap[i]);
}

// ---------------------------------------------------------------------------
// Kernel 3: finalize scalars
// ---------------------------------------------------------------------------
__global__ __launch_bounds__(1024) void lfq_finalize_kernel(float* __restrict__ out)
{
    int t = threadIdx.x;
    float ap = g_avg_probs[t] * (1.0f / (float)NPIX);
    float term = ap * logf(ap + 1e-5f);

    // block reduce
#pragma unroll
    for (int o = 16; o; o >>= 1)
        term += __shfl_xor_sync(0xFFFFFFFFu, term, o);
    __shared__ float red[32];
    if ((t & 31) == 0) red[t >> 5] = term;
    __syncthreads();
    if (t < 32) {
        float v = red[t];
#pragma unroll
        for (int o = 16; o; o >>= 1)
            v += __shfl_xor_sync(0xFFFFFFFFu, v, o);
        if (t == 0) {
            float avg_ent = -v;                                   // ENT_GAMMA = 1
            float pse     = g_pse_sum * (1.0f / (float)NPIX);
            float commit  = 0.25f * g_commit_sum * (1.0f / (float)NELEM);
            float ent_l   = 0.1f * (pse - avg_ent);               // ENT_WEIGHT = 0.1
            out[OUT_SCALARS + 0] = commit + ent_l;  // loss
            out[OUT_SCALARS + 1] = commit;          // commitment_loss
            out[OUT_SCALARS + 2] = ent_l;           // entropy_loss
            out[OUT_SCALARS + 3] = pse;             // per_sample_entropy
            out[OUT_SCALARS + 4] = avg_ent;         // avg_entropy
        }
    }
}

// ---------------------------------------------------------------------------
extern "C" void kernel_launch(void* const* d_in, const int* in_sizes, int n_in,
                              void* d_out, int out_size)
{
    const float* z   = (const float*)d_in[0];
    float*       out = (float*)d_out;
    (void)in_sizes; (void)n_in; (void)out_size;   // codebook is implicit (all 1024 sign patterns)

    lfq_init_kernel<<<1, 1024>>>();
    lfq_signidx_kernel<<<NPIX / 256, 256>>>(z, out);
    lfq_entropy_kernel<<<EBLOCKS, ETHREADS>>>(z);
    lfq_finalize_kernel<<<1, 1024>>>(out);
}

// round 2
// speedup vs baseline: 1.5887x; 1.5887x over previous
#include <cuda_runtime.h>
#include <cuda_bf16.h>
#include <cstdint>

// Problem constants
#define NPIX   65536      // 64 * 32 * 32 pixels
#define HW     1024       // 32*32
#define CCH    10         // channels / token bits
#define NCODE  1024       // 2^10
#define NELEM  655360     // 64*10*32*32

// Output layout (flattened reference tuple, fp32):
//  [0, 655360)   z_q_out ; [655360..655364] scalars ; [655365, 720901) indices
#define OUT_SCALARS 655360
#define OUT_IDX     655365

// 400 * log2(e): per-mismatched-channel penalty in log2 domain
#define CQ  577.0780163555854f
#define LN2 0.69314718055994531f

// Entropy kernel shape: 592 blocks = 4 per SM exactly, 8 warps each
#define EBLK 592
#define ETHR 256
#define EWPB 8
#define NWARPS (EBLK * EWPB)   // 4736, grid-stride over pixels

// Sign/index kernel: 4 pixels per thread
#define ABLK 64
#define ATHR 256

// Scratch (static __device__ — no allocations)
__device__ float g_avg_probs[NCODE];
__device__ float g_pse_sum;
__device__ float g_commit_parts[ABLK];

// ---------------- packed fp32 helpers (Blackwell f32x2) ----------------
__device__ __forceinline__ unsigned long long pk2(float a, float b) {
    unsigned long long r;
    asm("mov.b64 %0, {%1, %2};" : "=l"(r) : "f"(a), "f"(b));
    return r;
}
__device__ __forceinline__ void upk2(unsigned long long v, float& a, float& b) {
    asm("mov.b64 {%0, %1}, %2;" : "=f"(a), "=f"(b) : "l"(v));
}
__device__ __forceinline__ void ffma2(unsigned long long& acc,
                                      unsigned long long a, unsigned long long b) {
    asm("fma.rn.f32x2 %0, %1, %2, %0;" : "+l"(acc) : "l"(a), "l"(b));
}
__device__ __forceinline__ float ex2f(float x) {
    float r; asm("ex2.approx.f32 %0, %1;" : "=f"(r) : "f"(x)); return r;
}
__device__ __forceinline__ float rcpf(float x) {
    float r; asm("rcp.approx.f32 %0, %1;" : "=f"(r) : "f"(x)); return r;
}

// ---------------------------------------------------------------------------
// Kernel A: signs, indices, commitment partials; block 0 zeros scratch.
// 4 consecutive pixels per thread (float4).
// ---------------------------------------------------------------------------
__global__ __launch_bounds__(ATHR) void lfq_signidx_kernel(
    const float* __restrict__ z, float* __restrict__ out)
{
    int tid = threadIdx.x;
    if (blockIdx.x == 0) {          // zero scratch used by later kernels
        for (int i = tid; i < NCODE; i += ATHR) g_avg_probs[i] = 0.0f;
        if (tid == 0) g_pse_sum = 0.0f;
    }

    int p4  = blockIdx.x * ATHR + tid;       // handles pixels 4*p4 .. 4*p4+3
    int b   = p4 >> 8;
    int hw0 = (p4 << 2) & (HW - 1);
    const float* zp = z   + b * (CCH * HW) + hw0;
    float*       op = out + b * (CCH * HW) + hw0;

    int   idx0 = 0, idx1 = 0, idx2 = 0, idx3 = 0;
    float csum = 0.0f;
#pragma unroll
    for (int c = 0; c < CCH; c++) {
        float4 v = *(const float4*)(zp + c * HW);
        float4 o;
        o.x = v.x > 0.0f ? 1.0f : -1.0f;  idx0 |= (v.x > 0.0f) << c;
        o.y = v.y > 0.0f ? 1.0f : -1.0f;  idx1 |= (v.y > 0.0f) << c;
        o.z = v.z > 0.0f ? 1.0f : -1.0f;  idx2 |= (v.z > 0.0f) << c;
        o.w = v.w > 0.0f ? 1.0f : -1.0f;  idx3 |= (v.w > 0.0f) << c;
        float d0 = 1.0f - fabsf(v.x); csum = fmaf(d0, d0, csum);
        float d1 = 1.0f - fabsf(v.y); csum = fmaf(d1, d1, csum);
        float d2 = 1.0f - fabsf(v.z); csum = fmaf(d2, d2, csum);
        float d3 = 1.0f - fabsf(v.w); csum = fmaf(d3, d3, csum);
        *(float4*)(op + c * HW) = o;
    }
    float* ip = out + OUT_IDX + (p4 << 2);   // OUT_IDX unaligned: scalar stores
    ip[0] = (float)idx0; ip[1] = (float)idx1;
    ip[2] = (float)idx2; ip[3] = (float)idx3;

    // commitment: warp reduce, then block reduce, one partial per block
#pragma unroll
    for (int o = 16; o; o >>= 1)
        csum += __shfl_xor_sync(0xFFFFFFFFu, csum, o);
    __shared__ float s_red[ATHR / 32];
    if ((tid & 31) == 0) s_red[tid >> 5] = csum;
    __syncthreads();
    if (tid == 0) {
        float v = 0.0f;
#pragma unroll
        for (int w = 0; w < ATHR / 32; w++) v += s_red[w];
        g_commit_parts[blockIdx.x] = v;     // plain overwrite: no init needed
    }
}

// ---------------------------------------------------------------------------
// Kernel B: entropy. Warp per pixel; rank-1 softmax factorization.
//   code n = lo + 32*hi;  delta_n*log2e = b2[lo] + g2[hi],  both <= 0, max 0
//   b2[lo] = sum_{c<5}  min(+-CQ*z_c, 0)   (mismatch penalty, low bits)
//   g2[hi] = sum_{c>=5} min(+-CQ*z_c, 0)
//   e_n = eb_lo * Eh_hi;  Z = SB*SEh;  T2 = SBb*SEh + SB*SHh
// ---------------------------------------------------------------------------
__global__ __launch_bounds__(ETHR) void lfq_entropy_kernel(
    const float* __restrict__ z)
{
    __shared__ float s_ap[NCODE];
    __shared__ __align__(16) float s_x[EWPB][32];

    int tid  = threadIdx.x;
    int lane = tid & 31;
    int w    = tid >> 5;
    for (int i = tid; i < NCODE; i += ETHR) s_ap[i] = 0.0f;
    __syncthreads();

    // per-lane sign constants: lane bit (c%5) decides match direction
    float sgn[CCH];
#pragma unroll
    for (int c = 0; c < CCH; c++)
        sgn[c] = ((lane >> (c % 5)) & 1) ? CQ : -CQ;

    unsigned long long ap2[16];
#pragma unroll
    for (int k = 0; k < 16; k++) ap2[k] = 0ULL;
    float pse = 0.0f;

    int wid = blockIdx.x * EWPB + w;
    for (int p = wid; p < NPIX; p += NWARPS) {
        int b  = p >> 10;
        int hw = p & (HW - 1);
        const float* zp = z + b * (CCH * HW) + hw;

        float b2 = 0.0f, g2 = 0.0f;
#pragma unroll
        for (int c = 0; c < 5; c++) {
            float t = __ldg(zp + c * HW) * sgn[c];
            b2 += fminf(t, 0.0f);
        }
#pragma unroll
        for (int c = 5; c < CCH; c++) {
            float t = __ldg(zp + c * HW) * sgn[c];
            g2 += fminf(t, 0.0f);
        }

        float eb = ex2f(b2);          // lane as lo-half
        float Eh = ex2f(g2);          // lane as hi-half
        float p1 = eb * b2;
        float p2 = Eh * g2;

        float SB = eb, SE = Eh, S1 = p1, S2 = p2;
#pragma unroll
        for (int o = 16; o; o >>= 1) {
            SB += __shfl_xor_sync(0xFFFFFFFFu, SB, o);
            SE += __shfl_xor_sync(0xFFFFFFFFu, SE, o);
            S1 += __shfl_xor_sync(0xFFFFFFFFu, S1, o);
            S2 += __shfl_xor_sync(0xFFFFFFFFu, S2, o);
        }

        float Z    = SB * SE;                   // >= 1
        float s    = fmaf(SB, SE, -1.0f);       // Z - 1 >= 0
        float invZ = rcpf(Z);
        float T2   = fmaf(S1, SE, SB * S2);     // sum e * (delta*log2e)

        float lg;                                // ln(Z)
        if (s < 0.0625f)
            lg = s * (1.0f + s * (-0.5f + s * (0.33333334f + s * -0.25f)));
        else
            lg = logf(Z);
        pse += lg - LN2 * T2 * invZ;

        // avg_probs rank-1 accumulate: ap[lane][j] += (eb*invZ) * Eh_j
        float u = eb * invZ;
        s_x[w][lane] = Eh;
        __syncwarp();
        unsigned long long u2 = pk2(u, u);
        const unsigned long long* xq = (const unsigned long long*)s_x[w];
#pragma unroll
        for (int k = 0; k < 16; k++) ffma2(ap2[k], u2, xq[k]);
        __syncwarp();
    }

    if (lane == 0) atomicAdd(&g_pse_sum, pse);

    // flush: smem atomics (bank-conflict-free), then block -> global atomics
#pragma unroll
    for (int k = 0; k < 16; k++) {
        float a, bv; upk2(ap2[k], a, bv);
        atomicAdd(&s_ap[(2 * k)     * 32 + lane], a);
        atomicAdd(&s_ap[(2 * k + 1) * 32 + lane], bv);
    }
    __syncthreads();
    for (int i = tid; i < NCODE; i += ETHR)
        atomicAdd(&g_avg_probs[i], s_ap[i]);
}

// ---------------------------------------------------------------------------
// Kernel C: finalize scalars
// ---------------------------------------------------------------------------
__global__ __launch_bounds__(1024) void lfq_finalize_kernel(float* __restrict__ out)
{
    int t = threadIdx.x;
    float ap   = g_avg_probs[t] * (1.0f / (float)NPIX);
    float term = ap * logf(ap + 1e-5f);

#pragma unroll
    for (int o = 16; o; o >>= 1)
        term += __shfl_xor_sync(0xFFFFFFFFu, term, o);
    __shared__ float red[32];
    __shared__ float s_commit;
    if (t == 0) s_commit = 0.0f;
    if ((t & 31) == 0) red[t >> 5] = term;
    __syncthreads();
    if (t < ABLK) atomicAdd(&s_commit, g_commit_parts[t]);
    __syncthreads();
    if (t < 32) {
        float v = red[t];
#pragma unroll
        for (int o = 16; o; o >>= 1)
            v += __shfl_xor_sync(0xFFFFFFFFu, v, o);
        if (t == 0) {
            float avg_ent = -v;
            float pse     = g_pse_sum * (1.0f / (float)NPIX);
            float commit  = 0.25f * s_commit * (1.0f / (float)NELEM);
            float ent_l   = 0.1f * (pse - avg_ent);
            out[OUT_SCALARS + 0] = commit + ent_l;
            out[OUT_SCALARS + 1] = commit;
            out[OUT_SCALARS + 2] = ent_l;
            out[OUT_SCALARS + 3] = pse;
            out[OUT_SCALARS + 4] = avg_ent;
        }
    }
}

// ---------------------------------------------------------------------------
extern "C" void kernel_launch(void* const* d_in, const int* in_sizes, int n_in,
                              void* d_out, int out_size)
{
    const float* z   = (const float*)d_in[0];
    float*       out = (float*)d_out;
    (void)in_sizes; (void)n_in; (void)out_size;

    lfq_signidx_kernel<<<ABLK, ATHR>>>(z, out);
    lfq_entropy_kernel<<<EBLK, ETHR>>>(z);
    lfq_finalize_kernel<<<1, 1024>>>(out);
}